// round 1
// baseline (speedup 1.0000x reference)
#include <cuda_runtime.h>
#include <cuda_bf16.h>
#include <math.h>

// Problem constants (fixed by the reference)
#define NTOK   4096      // B*T = 2*2048
#define DMODEL 1024
#define DICT   16384
#define TOPK   8

// ---------------------------------------------------------------------------
// Scratch (allocation-free rule: __device__ globals)
// ---------------------------------------------------------------------------
__device__ float g_coeffs[(size_t)NTOK * DICT];   // 256 MB
__device__ float g_vals[NTOK * TOPK];
__device__ int   g_idx[NTOK * TOPK];
__device__ float g_tokloss[NTOK];

// ---------------------------------------------------------------------------
// Kernel 1: fp32 SGEMM  C[m,n] = sum_d x[m,d] * W_enc[n,d]   (NT gemm)
// BM=BN=128, BK=16, 256 threads, 8x8 per thread
// ---------------------------------------------------------------------------
#define BM 128
#define BN 128
#define BK 16
#define TM 8
#define TN 8

__global__ __launch_bounds__(256, 2)
void gemm_kernel(const float* __restrict__ A, const float* __restrict__ Bw) {
    __shared__ float As[BK][BM];   // transposed tiles: [k][m]
    __shared__ float Bs[BK][BN];

    const int tid = threadIdx.x;
    const int tx = tid & 15;        // 0..15 -> n
    const int ty = tid >> 4;        // 0..15 -> m
    const int m0 = blockIdx.y * BM;
    const int n0 = blockIdx.x * BN;

    float acc[TM][TN];
    #pragma unroll
    for (int i = 0; i < TM; i++)
        #pragma unroll
        for (int j = 0; j < TN; j++) acc[i][j] = 0.f;

    for (int k0 = 0; k0 < DMODEL; k0 += BK) {
        // Load 128x16 tiles of A and B (float4 along k), store transposed.
        #pragma unroll
        for (int l = 0; l < 2; l++) {
            int lin = tid + l * 256;          // 0..511
            int row = lin >> 2;               // 0..127
            int kq  = (lin & 3) * 4;          // 0,4,8,12
            float4 va = *reinterpret_cast<const float4*>(
                &A[(size_t)(m0 + row) * DMODEL + k0 + kq]);
            As[kq + 0][row] = va.x; As[kq + 1][row] = va.y;
            As[kq + 2][row] = va.z; As[kq + 3][row] = va.w;
            float4 vb = *reinterpret_cast<const float4*>(
                &Bw[(size_t)(n0 + row) * DMODEL + k0 + kq]);
            Bs[kq + 0][row] = vb.x; Bs[kq + 1][row] = vb.y;
            Bs[kq + 2][row] = vb.z; Bs[kq + 3][row] = vb.w;
        }
        __syncthreads();

        #pragma unroll
        for (int kk = 0; kk < BK; kk++) {
            float a[TM], b[TN];
            // vectorized smem reads (LDS.128) to dodge bank conflicts
            float4 a0 = *reinterpret_cast<const float4*>(&As[kk][ty * TM]);
            float4 a1 = *reinterpret_cast<const float4*>(&As[kk][ty * TM + 4]);
            float4 b0 = *reinterpret_cast<const float4*>(&Bs[kk][tx * TN]);
            float4 b1 = *reinterpret_cast<const float4*>(&Bs[kk][tx * TN + 4]);
            a[0]=a0.x; a[1]=a0.y; a[2]=a0.z; a[3]=a0.w;
            a[4]=a1.x; a[5]=a1.y; a[6]=a1.z; a[7]=a1.w;
            b[0]=b0.x; b[1]=b0.y; b[2]=b0.z; b[3]=b0.w;
            b[4]=b1.x; b[5]=b1.y; b[6]=b1.z; b[7]=b1.w;
            #pragma unroll
            for (int i = 0; i < TM; i++)
                #pragma unroll
                for (int j = 0; j < TN; j++)
                    acc[i][j] = fmaf(a[i], b[j], acc[i][j]);
        }
        __syncthreads();
    }

    #pragma unroll
    for (int i = 0; i < TM; i++) {
        int m = m0 + ty * TM + i;
        #pragma unroll
        for (int j = 0; j < TN; j += 4) {
            float4 v = make_float4(acc[i][j], acc[i][j+1], acc[i][j+2], acc[i][j+3]);
            *reinterpret_cast<float4*>(
                &g_coeffs[(size_t)m * DICT + n0 + tx * TN + j]) = v;
        }
    }
}

// ---------------------------------------------------------------------------
// Kernel 2: per-token top-8 (block = 1 token, 256 threads)
// Deterministic: tie-break by lowest index everywhere.
// ---------------------------------------------------------------------------
__global__ __launch_bounds__(256)
void topk_kernel() {
    const int token = blockIdx.x;
    const float* __restrict__ row = g_coeffs + (size_t)token * DICT;
    const int tid = threadIdx.x;
    const int lane = tid & 31;
    const int wid = tid >> 5;

    float lv[TOPK];
    int   li[TOPK];
    #pragma unroll
    for (int i = 0; i < TOPK; i++) { lv[i] = -3.4e38f; li[i] = 0x7fffffff; }

    // strided scan: each thread keeps a sorted-desc local top-8
    for (int j = tid; j < DICT; j += 256) {
        float v = row[j];
        if (v > lv[TOPK - 1]) {
            int pos = TOPK - 1;
            #pragma unroll
            for (int s = TOPK - 1; s > 0; s--) {
                if (lv[s - 1] < v) { lv[s] = lv[s - 1]; li[s] = li[s - 1]; pos = s - 1; }
            }
            lv[pos] = v; li[pos] = j;
        }
    }

    __shared__ float wv[8];
    __shared__ int   wi[8];
    __shared__ float sbv;
    __shared__ int   sbi;

    int p = 0;
    float run = 0.f;

    for (int r = 0; r < TOPK; r++) {
        float v = (p < TOPK) ? lv[p] : -3.4e38f;
        int   i = (p < TOPK) ? li[p] : 0x7fffffff;
        // warp argmax (tie -> lower index)
        #pragma unroll
        for (int off = 16; off > 0; off >>= 1) {
            float ov = __shfl_down_sync(0xffffffffu, v, off);
            int   oi = __shfl_down_sync(0xffffffffu, i, off);
            if (ov > v || (ov == v && oi < i)) { v = ov; i = oi; }
        }
        if (lane == 0) { wv[wid] = v; wi[wid] = i; }
        __syncthreads();
        if (tid == 0) {
            float bv = wv[0]; int bi = wi[0];
            #pragma unroll
            for (int w = 1; w < 8; w++)
                if (wv[w] > bv || (wv[w] == bv && wi[w] < bi)) { bv = wv[w]; bi = wi[w]; }
            sbv = bv; sbi = bi;
            g_vals[token * TOPK + r] = bv;
            g_idx[token * TOPK + r]  = bi;
            run += fabsf(bv);
        }
        __syncthreads();
        if (p < TOPK && li[p] == sbi) p++;   // winner pops (indices unique per thread)
        __syncthreads();
    }
    if (tid == 0) g_tokloss[token] = run;
}

// ---------------------------------------------------------------------------
// Kernel 3: offset[token][d] = sum_k v_k * W_dict[idx_k][d]
// block = 1 token, 256 threads, float4 per thread over 1024 dims
// ---------------------------------------------------------------------------
__global__ __launch_bounds__(256)
void gather_kernel(const float* __restrict__ Wd, float* __restrict__ out) {
    const int token = blockIdx.x;
    const int tid = threadIdx.x;
    __shared__ float sv[TOPK];
    __shared__ int   si[TOPK];
    if (tid < TOPK) { sv[tid] = g_vals[token * TOPK + tid]; si[tid] = g_idx[token * TOPK + tid]; }
    __syncthreads();

    int d = tid * 4;
    float4 acc = make_float4(0.f, 0.f, 0.f, 0.f);
    #pragma unroll
    for (int k = 0; k < TOPK; k++) {
        const float4 w = *reinterpret_cast<const float4*>(
            &Wd[(size_t)si[k] * DMODEL + d]);
        float v = sv[k];
        acc.x = fmaf(v, w.x, acc.x);
        acc.y = fmaf(v, w.y, acc.y);
        acc.z = fmaf(v, w.z, acc.z);
        acc.w = fmaf(v, w.w, acc.w);
    }
    *reinterpret_cast<float4*>(&out[(size_t)token * DMODEL + d]) = acc;
}

// ---------------------------------------------------------------------------
// Kernel 4: sparsity loss = sum_t tokloss[t] / (NTOK * DICT), fixed-order tree
// ---------------------------------------------------------------------------
__global__ __launch_bounds__(256)
void loss_kernel(float* __restrict__ out, int out_size) {
    __shared__ float s[256];
    float acc = 0.f;
    for (int i = threadIdx.x; i < NTOK; i += 256) acc += g_tokloss[i];
    s[threadIdx.x] = acc;
    __syncthreads();
    for (int st = 128; st > 0; st >>= 1) {
        if (threadIdx.x < st) s[threadIdx.x] += s[threadIdx.x + st];
        __syncthreads();
    }
    if (threadIdx.x == 0 && out_size > NTOK * DMODEL) {
        out[out_size - 1] = s[0] / ((float)NTOK * (float)DICT);
    }
}

// ---------------------------------------------------------------------------
extern "C" void kernel_launch(void* const* d_in, const int* in_sizes, int n_in,
                              void* d_out, int out_size) {
    const float* x      = (const float*)d_in[0];   // [4096, 1024]
    const float* W_enc  = (const float*)d_in[1];   // [16384, 1024]
    const float* W_dict = (const float*)d_in[2];   // [16384, 1024]
    float* out = (float*)d_out;

    dim3 ggrid(DICT / BN, NTOK / BM);              // (128, 32)
    gemm_kernel<<<ggrid, 256>>>(x, W_enc);
    topk_kernel<<<NTOK, 256>>>();
    gather_kernel<<<NTOK, 256>>>(W_dict, out);
    loss_kernel<<<1, 256>>>(out, out_size);
}

// round 3
// speedup vs baseline: 1.9655x; 1.9655x over previous
#include <cuda_runtime.h>
#include <cuda_bf16.h>
#include <math.h>
#include <stdint.h>

// Problem constants
#define NTOK   4096
#define DMODEL 1024
#define DICT   16384
#define TOPK   8
#define TOPC   16      // candidates kept before fp32 rescore

// ---------------------------------------------------------------------------
// Scratch (__device__ globals; no allocation allowed)
// ---------------------------------------------------------------------------
__device__ __nv_bfloat16 g_xb[(size_t)NTOK * DMODEL];     // 8 MB
__device__ __nv_bfloat16 g_wb[(size_t)DICT * DMODEL];     // 32 MB
__device__ __nv_bfloat16 g_cb[(size_t)NTOK * DICT];       // 128 MB (bf16 coeffs)
__device__ int   g_cand[NTOK * TOPC];
__device__ float g_vals[NTOK * TOPK];
__device__ int   g_idx[NTOK * TOPK];
__device__ float g_tokloss[NTOK];

// ---------------------------------------------------------------------------
// PTX helpers (sm_80-level only: ldmatrix / mma.sync / cp.async — all legal
// at virtual arch compute_103, unlike tcgen05.*)
// ---------------------------------------------------------------------------
__device__ __forceinline__ uint32_t smem_to_u32(const void* p) {
    uint32_t a;
    asm("{ .reg .u64 t; cvta.to.shared.u64 t, %1; cvt.u32.u64 %0, t; }"
        : "=r"(a) : "l"(p));
    return a;
}
__device__ __forceinline__ void cp_async16(uint32_t dst, const void* src) {
    asm volatile("cp.async.cg.shared.global [%0], [%1], 16;" :: "r"(dst), "l"(src));
}
#define CP_COMMIT() asm volatile("cp.async.commit_group;" ::: "memory")
#define CP_WAIT(n)  asm volatile("cp.async.wait_group %0;" :: "n"(n) : "memory")

__device__ __forceinline__ void ldsm_x4(uint32_t* r, uint32_t addr) {
    asm volatile("ldmatrix.sync.aligned.m8n8.x4.shared.b16 {%0,%1,%2,%3}, [%4];"
        : "=r"(r[0]), "=r"(r[1]), "=r"(r[2]), "=r"(r[3]) : "r"(addr));
}
__device__ __forceinline__ void ldsm_x2(uint32_t* r, uint32_t addr) {
    asm volatile("ldmatrix.sync.aligned.m8n8.x2.shared.b16 {%0,%1}, [%2];"
        : "=r"(r[0]), "=r"(r[1]) : "r"(addr));
}
__device__ __forceinline__ void mma_bf16(float* d, const uint32_t* a,
                                         const uint32_t* b, const float* c) {
    asm volatile("mma.sync.aligned.m16n8k16.row.col.f32.bf16.bf16.f32 "
        "{%0,%1,%2,%3}, {%4,%5,%6,%7}, {%8,%9}, {%10,%11,%12,%13};"
        : "=f"(d[0]), "=f"(d[1]), "=f"(d[2]), "=f"(d[3])
        : "r"(a[0]), "r"(a[1]), "r"(a[2]), "r"(a[3]),
          "r"(b[0]), "r"(b[1]),
          "f"(c[0]), "f"(c[1]), "f"(c[2]), "f"(c[3]));
}

// ---------------------------------------------------------------------------
// Kernel 0: fp32 -> bf16 conversion
// ---------------------------------------------------------------------------
__global__ __launch_bounds__(256)
void conv_kernel(const float* __restrict__ in, __nv_bfloat16* __restrict__ out, int n4) {
    int i = blockIdx.x * 256 + threadIdx.x;
    if (i >= n4) return;
    float4 v = reinterpret_cast<const float4*>(in)[i];
    __nv_bfloat162 a = __floats2bfloat162_rn(v.x, v.y);
    __nv_bfloat162 b = __floats2bfloat162_rn(v.z, v.w);
    uint2 o;
    o.x = *reinterpret_cast<uint32_t*>(&a);
    o.y = *reinterpret_cast<uint32_t*>(&b);
    reinterpret_cast<uint2*>(out)[i] = o;
}

// ---------------------------------------------------------------------------
// Kernel 1: HMMA bf16 GEMM  C_bf16[m,n] = sum_d xb[m,d] * wb[n,d]
// CTA 128x128, K-chunk 32, double-buffered cp.async, 8 warps (2x4),
// warp tile 64x32, mma.sync.m16n8k16 bf16 -> fp32
// ---------------------------------------------------------------------------
#define KC    32
#define NIT   (DMODEL / KC)        // 32
#define ROWB  80                   // smem row stride bytes (40 bf16: 32 data + 8 pad)
#define TILEB (128 * ROWB)         // 10240 B per operand tile

__global__ __launch_bounds__(256, 2)
void gemm_kernel(const __nv_bfloat16* __restrict__ A, const __nv_bfloat16* __restrict__ B,
                 __nv_bfloat16* __restrict__ C) {
    __shared__ __align__(128) char sm[2 * 2 * TILEB];   // [stage][A|B]
    const uint32_t smb = smem_to_u32(sm);
    const int tid  = threadIdx.x;
    const int wid  = tid >> 5;
    const int lane = tid & 31;
    const int wm   = wid >> 2;          // 0..1  -> 64 rows of m
    const int wn   = wid & 3;           // 0..3  -> 32 cols of n
    const int m0   = blockIdx.y * 128;
    const int n0   = blockIdx.x * 128;

    float acc[4][4][4];
    #pragma unroll
    for (int i = 0; i < 4; i++)
        #pragma unroll
        for (int j = 0; j < 4; j++)
            #pragma unroll
            for (int q = 0; q < 4; q++) acc[i][j][q] = 0.f;

    // ---- stage loader: 4 x cp.async(16B) per thread (2 A + 2 B)
    auto load_stage = [&](int it) {
        const int s = it & 1;
        const uint32_t aOff = smb + s * 2 * TILEB;
        const uint32_t bOff = aOff + TILEB;
        const int k0 = it * KC;
        #pragma unroll
        for (int i = 0; i < 2; i++) {
            int c = tid + i * 256;          // 0..511
            int row = c >> 2;               // 0..127
            int q = c & 3;                  // 16B chunk within 64B row
            cp_async16(aOff + row * ROWB + q * 16,
                       A + (size_t)(m0 + row) * DMODEL + k0 + q * 8);
            cp_async16(bOff + row * ROWB + q * 16,
                       B + (size_t)(n0 + row) * DMODEL + k0 + q * 8);
        }
        CP_COMMIT();
    };

    load_stage(0);

    for (int s = 0; s < NIT; s++) {
        if (s + 1 < NIT) {
            load_stage(s + 1);
            CP_WAIT(1);
        } else {
            CP_WAIT(0);
        }
        __syncthreads();

        const uint32_t aOff = smb + (s & 1) * 2 * TILEB;
        const uint32_t bOff = aOff + TILEB;

        #pragma unroll
        for (int kk = 0; kk < KC; kk += 16) {
            uint32_t af[4][4], bf[4][2];
            #pragma unroll
            for (int mi = 0; mi < 4; mi++) {
                int row = wm * 64 + mi * 16 + (lane & 15);
                ldsm_x4(af[mi], aOff + row * ROWB + kk * 2 + (lane >> 4) * 16);
            }
            #pragma unroll
            for (int ni = 0; ni < 4; ni++) {
                int row = wn * 32 + ni * 8 + (lane & 7);
                ldsm_x2(bf[ni], bOff + row * ROWB + kk * 2 + ((lane >> 3) & 1) * 16);
            }
            #pragma unroll
            for (int mi = 0; mi < 4; mi++)
                #pragma unroll
                for (int ni = 0; ni < 4; ni++)
                    mma_bf16(acc[mi][ni], af[mi], bf[ni], acc[mi][ni]);
        }
        __syncthreads();
    }

    // ---- epilogue: fp32 -> bf16, direct gmem stores (bf16x2 per store)
    #pragma unroll
    for (int mi = 0; mi < 4; mi++) {
        #pragma unroll
        for (int ni = 0; ni < 4; ni++) {
            int m = m0 + wm * 64 + mi * 16 + (lane >> 2);
            int n = n0 + wn * 32 + ni * 8 + (lane & 3) * 2;
            __nv_bfloat162 h0 = __floats2bfloat162_rn(acc[mi][ni][0], acc[mi][ni][1]);
            __nv_bfloat162 h1 = __floats2bfloat162_rn(acc[mi][ni][2], acc[mi][ni][3]);
            *reinterpret_cast<__nv_bfloat162*>(C + (size_t)m * DICT + n) = h0;
            *reinterpret_cast<__nv_bfloat162*>(C + (size_t)(m + 8) * DICT + n) = h1;
        }
    }
}

// ---------------------------------------------------------------------------
// Kernel 2: per-token top-16 candidates from bf16 coeffs (block = 1 token)
// ---------------------------------------------------------------------------
__global__ __launch_bounds__(256)
void topc_kernel() {
    const int token = blockIdx.x;
    const __nv_bfloat16* __restrict__ row = g_cb + (size_t)token * DICT;
    const int tid = threadIdx.x;
    const int lane = tid & 31;
    const int wid = tid >> 5;

    float lv[TOPC];
    int   li[TOPC];
    #pragma unroll
    for (int i = 0; i < TOPC; i++) { lv[i] = -3.4e38f; li[i] = 0x7fffffff; }

    // each thread scans 64 elems: 8 iters x 8 bf16 (16B coalesced)
    for (int itr = 0; itr < 8; itr++) {
        int j0 = (itr * 256 + tid) * 8;
        float4 raw = *reinterpret_cast<const float4*>(row + j0);
        const __nv_bfloat162* h = reinterpret_cast<const __nv_bfloat162*>(&raw);
        #pragma unroll
        for (int e = 0; e < 4; e++) {
            float v0 = __bfloat162float(h[e].x);
            float v1 = __bfloat162float(h[e].y);
            #pragma unroll
            for (int t = 0; t < 2; t++) {
                float v = t ? v1 : v0;
                int j = j0 + e * 2 + t;
                if (v > lv[TOPC - 1]) {
                    int pos = TOPC - 1;
                    #pragma unroll
                    for (int s = TOPC - 1; s > 0; s--) {
                        if (lv[s - 1] < v) { lv[s] = lv[s - 1]; li[s] = li[s - 1]; pos = s - 1; }
                    }
                    lv[pos] = v; li[pos] = j;
                }
            }
        }
    }

    __shared__ float wv[8];
    __shared__ int   wi[8];
    __shared__ int   sbi;

    int p = 0;
    for (int r = 0; r < TOPC; r++) {
        float v = (p < TOPC) ? lv[p] : -3.4e38f;
        int   i = (p < TOPC) ? li[p] : 0x7fffffff;
        #pragma unroll
        for (int off = 16; off > 0; off >>= 1) {
            float ov = __shfl_down_sync(0xffffffffu, v, off);
            int   oi = __shfl_down_sync(0xffffffffu, i, off);
            if (ov > v || (ov == v && oi < i)) { v = ov; i = oi; }
        }
        if (lane == 0) { wv[wid] = v; wi[wid] = i; }
        __syncthreads();
        if (tid == 0) {
            float bv = wv[0]; int bi = wi[0];
            #pragma unroll
            for (int w = 1; w < 8; w++)
                if (wv[w] > bv || (wv[w] == bv && wi[w] < bi)) { bv = wv[w]; bi = wi[w]; }
            sbi = bi;
            g_cand[token * TOPC + r] = bi;
        }
        __syncthreads();
        if (p < TOPC && li[p] == sbi) p++;
        __syncthreads();
    }
}

// ---------------------------------------------------------------------------
// Kernel 3: exact fp32 rescore of 16 candidates + top-8 select (block = token)
// ---------------------------------------------------------------------------
__global__ __launch_bounds__(256)
void rescore_kernel(const float* __restrict__ x, const float* __restrict__ W) {
    const int token = blockIdx.x;
    const int tid = threadIdx.x;
    const int lane = tid & 31;
    const int wid = tid >> 5;
    __shared__ float sx[DMODEL];
    __shared__ float cv[TOPC];
    __shared__ int   ci[TOPC];

    reinterpret_cast<float4*>(sx)[tid] = reinterpret_cast<const float4*>(
        x + (size_t)token * DMODEL)[tid];
    if (tid < TOPC) ci[tid] = g_cand[token * TOPC + tid];
    __syncthreads();

    #pragma unroll
    for (int cc = 0; cc < 2; cc++) {
        int c = wid * 2 + cc;
        const float4* wr = reinterpret_cast<const float4*>(W + (size_t)ci[c] * DMODEL);
        const float4* sx4 = reinterpret_cast<const float4*>(sx);
        float acc = 0.f;
        #pragma unroll
        for (int i = 0; i < 8; i++) {
            float4 a = sx4[lane + i * 32];
            float4 b = wr[lane + i * 32];
            acc = fmaf(a.x, b.x, acc);
            acc = fmaf(a.y, b.y, acc);
            acc = fmaf(a.z, b.z, acc);
            acc = fmaf(a.w, b.w, acc);
        }
        #pragma unroll
        for (int off = 16; off > 0; off >>= 1)
            acc += __shfl_xor_sync(0xffffffffu, acc, off);
        if (lane == 0) cv[c] = acc;
    }
    __syncthreads();

    if (tid == 0) {
        float v[TOPC]; int ix[TOPC];
        #pragma unroll
        for (int i = 0; i < TOPC; i++) { v[i] = cv[i]; ix[i] = ci[i]; }
        float run = 0.f;
        #pragma unroll
        for (int r = 0; r < TOPK; r++) {
            int best = 0;
            #pragma unroll
            for (int i = 1; i < TOPC; i++)
                if (v[i] > v[best] || (v[i] == v[best] && ix[i] < ix[best])) best = i;
            g_vals[token * TOPK + r] = v[best];
            g_idx[token * TOPK + r]  = ix[best];
            run += fabsf(v[best]);
            v[best] = -3.4e38f;
        }
        g_tokloss[token] = run;
    }
}

// ---------------------------------------------------------------------------
// Kernel 4: offset[token][d] = sum_k v_k * W_dict[idx_k][d]
// ---------------------------------------------------------------------------
__global__ __launch_bounds__(256)
void gather_kernel(const float* __restrict__ Wd, float* __restrict__ out) {
    const int token = blockIdx.x;
    const int tid = threadIdx.x;
    __shared__ float sv[TOPK];
    __shared__ int   si[TOPK];
    if (tid < TOPK) { sv[tid] = g_vals[token * TOPK + tid]; si[tid] = g_idx[token * TOPK + tid]; }
    __syncthreads();

    int d = tid * 4;
    float4 acc = make_float4(0.f, 0.f, 0.f, 0.f);
    #pragma unroll
    for (int k = 0; k < TOPK; k++) {
        const float4 w = *reinterpret_cast<const float4*>(&Wd[(size_t)si[k] * DMODEL + d]);
        float v = sv[k];
        acc.x = fmaf(v, w.x, acc.x);
        acc.y = fmaf(v, w.y, acc.y);
        acc.z = fmaf(v, w.z, acc.z);
        acc.w = fmaf(v, w.w, acc.w);
    }
    *reinterpret_cast<float4*>(&out[(size_t)token * DMODEL + d]) = acc;
}

// ---------------------------------------------------------------------------
// Kernel 5: sparsity loss (fixed-order tree reduction)
// ---------------------------------------------------------------------------
__global__ __launch_bounds__(256)
void loss_kernel(float* __restrict__ out, int out_size) {
    __shared__ float s[256];
    float acc = 0.f;
    for (int i = threadIdx.x; i < NTOK; i += 256) acc += g_tokloss[i];
    s[threadIdx.x] = acc;
    __syncthreads();
    for (int st = 128; st > 0; st >>= 1) {
        if (threadIdx.x < st) s[threadIdx.x] += s[threadIdx.x + st];
        __syncthreads();
    }
    if (threadIdx.x == 0 && out_size > NTOK * DMODEL) {
        out[out_size - 1] = s[0] / ((float)NTOK * (float)DICT);
    }
}

// ---------------------------------------------------------------------------
extern "C" void kernel_launch(void* const* d_in, const int* in_sizes, int n_in,
                              void* d_out, int out_size) {
    const float* x      = (const float*)d_in[0];   // [4096, 1024]
    const float* W_enc  = (const float*)d_in[1];   // [16384, 1024]
    const float* W_dict = (const float*)d_in[2];   // [16384, 1024]
    float* out = (float*)d_out;

    __nv_bfloat16 *xb, *wb, *cb;
    cudaGetSymbolAddress((void**)&xb, g_xb);
    cudaGetSymbolAddress((void**)&wb, g_wb);
    cudaGetSymbolAddress((void**)&cb, g_cb);

    conv_kernel<<<(NTOK * DMODEL / 4 + 255) / 256, 256>>>(x, xb, NTOK * DMODEL / 4);
    conv_kernel<<<(DICT * DMODEL / 4 + 255) / 256, 256>>>(W_enc, wb, DICT * DMODEL / 4);

    dim3 ggrid(DICT / 128, NTOK / 128);            // (128, 32)
    gemm_kernel<<<ggrid, 256>>>(xb, wb, cb);

    topc_kernel<<<NTOK, 256>>>();
    rescore_kernel<<<NTOK, 256>>>(x, W_enc);
    gather_kernel<<<NTOK, 256>>>(W_dict, out);
    loss_kernel<<<1, 256>>>(out, out_size);
}